// round 14
// baseline (speedup 1.0000x reference)
#include <cuda_runtime.h>
#include <cuda_fp16.h>
#include <cstdint>
#include <cstddef>

// ============================================================
// UUPBitLinear: out = round(clip(x @ (sign(W-mean)*gamma) + bias, -1, 1)*7)/7
//   x: [65536, 512] fp32, W: [512, 512] fp32, bias: [512] fp32
//
// HMMA mma.sync path. gamma factored out -> B operand is exact ternary fp16
// S^T. x pre-split into hi/lo fp16; fp32-accumulated two-pass MMA.
// R13: R5 shape (256 thr, warp 32x32, BN=64) + intra-warp fragment double
//      buffering: ks1's LDSM burst is issued BEFORE ks0's MMA block, so the
//      smem crossbar runs concurrently with the tensor pipe inside every
//      warp (R5-R12 showed they were serializing: elapsed ~= tensor + L1).
//      Costs ~106 regs -> 2 CTAs/SM; compensate with 4 cp.async stages.
// ============================================================

#define M_TOTAL 65536
#define N_TOTAL 512
#define K_TOTAL 512

#define BM 128
#define BN 64
#define BK 32
#define KB_STEPS (K_TOTAL / BK)   // 16
#define STAGES 4

// dynamic smem: [0,256) bias; stages at 1024 + s*20480
//   A_hi: 128 rows x 64B = 8192 ; A_lo: 8192 ; B: 64 rows x 64B = 4096
#define OFF_BIAS   0
#define STAGE_SZ   20480
#define OFF_AHI(s) (1024 + (s) * STAGE_SZ)
#define OFF_ALO(s) (1024 + (s) * STAGE_SZ + 8192)
#define OFF_BT(s)  (1024 + (s) * STAGE_SZ + 16384)
#define SMEM_TOTAL (1024 + STAGES * STAGE_SZ)   // 82944 -> 2 CTAs/SM

// ---- device scratch (allocation-free) ----
__device__ float  g_part_sum[512];
__device__ float  g_part_abs[512];
__device__ float  g_gamma;
__device__ __half g_ST[N_TOTAL * K_TOTAL];            // S^T: [N][K] ternary fp16
__device__ __half g_xhi[(size_t)M_TOTAL * K_TOTAL];   // 64 MB
__device__ __half g_xlo[(size_t)M_TOTAL * K_TOTAL];   // 64 MB

// ---- helpers ----
__device__ __forceinline__ uint32_t smem_u32(const void* p) {
    uint32_t a;
    asm("{ .reg .u64 t; cvta.to.shared.u64 t, %1; cvt.u32.u64 %0, t; }"
        : "=r"(a) : "l"(p));
    return a;
}

// rows are 64B (32 halfs); chunk = 16B unit (0..3), swizzled so ldmatrix's
// 8-row groups hit distinct banks (validated R3-R12).
__device__ __forceinline__ uint32_t sw_off(int row, int chunk) {
    return (uint32_t)(row * 64 + (((chunk ^ ((row >> 1) & 3)) & 3) << 4));
}

#define LDSM_X4(r0, r1, r2, r3, addr)                                      \
    asm volatile("ldmatrix.sync.aligned.m8n8.x4.shared.b16 "               \
                 "{%0,%1,%2,%3}, [%4];"                                    \
                 : "=r"(r0), "=r"(r1), "=r"(r2), "=r"(r3) : "r"(addr))

#define MMA16816(d, a0, a1, a2, a3, b0, b1)                                \
    asm volatile("mma.sync.aligned.m16n8k16.row.col.f32.f16.f16.f32 "      \
                 "{%0,%1,%2,%3}, {%4,%5,%6,%7}, {%8,%9}, {%0,%1,%2,%3};"   \
                 : "+f"((d)[0]), "+f"((d)[1]), "+f"((d)[2]), "+f"((d)[3])  \
                 : "r"(a0), "r"(a1), "r"(a2), "r"(a3), "r"(b0), "r"(b1))

#define CP16(smaddr, gptr)                                                 \
    asm volatile("cp.async.cg.shared.global [%0], [%1], 16;"               \
                 :: "r"(smaddr), "l"(__cvta_generic_to_global(gptr)) : "memory")

#define CP_COMMIT() asm volatile("cp.async.commit_group;" ::: "memory")
#define CP_WAIT2()  asm volatile("cp.async.wait_group 2;" ::: "memory")

__device__ __forceinline__ uint32_t pack_h2(__half a, __half b) {
    __half2 h = __halves2half2(a, b);
    return *reinterpret_cast<uint32_t*>(&h);
}

__device__ __forceinline__ float quantize(float y) {
    y = fminf(fmaxf(y, -1.0f), 1.0f);
    return rintf(y * 7.0f) * (1.0f / 7.0f);   // round-half-even == jnp.round
}

// ---- prep 1: deterministic per-row reduction of W ----
__global__ void reduce_rows(const float* __restrict__ w) {
    __shared__ float ss[256], sa[256];
    int r = blockIdx.x, t = threadIdx.x;
    float v0 = w[r * 512 + t];
    float v1 = w[r * 512 + t + 256];
    ss[t] = v0 + v1;
    sa[t] = fabsf(v0) + fabsf(v1);
    __syncthreads();
    #pragma unroll
    for (int o = 128; o > 0; o >>= 1) {
        if (t < o) { ss[t] += ss[t + o]; sa[t] += sa[t + o]; }
        __syncthreads();
    }
    if (t == 0) { g_part_sum[r] = ss[0]; g_part_abs[r] = sa[0]; }
}

// ---- prep 2: fused final reduce + pack S^T[n][k] = sign(W[k][n]-mean) ----
__global__ void __launch_bounds__(512)
pack_signs(const float* __restrict__ w) {
    __shared__ float ss[256], sa[256];
    __shared__ float sh_mean;
    const int t = threadIdx.x;
    const int n = blockIdx.x;
    if (t < 256) {
        ss[t] = g_part_sum[t] + g_part_sum[t + 256];
        sa[t] = g_part_abs[t] + g_part_abs[t + 256];
    }
    __syncthreads();
    #pragma unroll
    for (int o = 128; o > 0; o >>= 1) {
        if (t < o) { ss[t] += ss[t + o]; sa[t] += sa[t + o]; }
        __syncthreads();
    }
    if (t == 0) {
        sh_mean = ss[0] * (1.0f / 262144.0f);
        if (n == 0) g_gamma = sa[0] * (1.0f / 262144.0f);
    }
    __syncthreads();
    const float mean = sh_mean;
    float d = w[t * 512 + n] - mean;
    float s = (d > 0.0f) ? 1.0f : ((d < 0.0f) ? -1.0f : 0.0f);
    g_ST[n * 512 + t] = __float2half(s);
}

// ---- prep 3: split x into fp16 hi/lo (exact 2-term decomposition) ----
__global__ void __launch_bounds__(256)
split_x(const float* __restrict__ x) {
    size_t i = ((size_t)blockIdx.x * 256 + threadIdx.x) * 8;
    float4 a = *reinterpret_cast<const float4*>(x + i);
    float4 b = *reinterpret_cast<const float4*>(x + i + 4);
    float f[8] = {a.x, a.y, a.z, a.w, b.x, b.y, b.z, b.w};
    uint32_t hi[4], lo[4];
    #pragma unroll
    for (int j = 0; j < 4; j++) {
        float u = f[2 * j], v = f[2 * j + 1];
        __half hu = __float2half_rn(u), hv = __float2half_rn(v);
        __half lu = __float2half_rn(u - __half2float(hu));
        __half lv = __float2half_rn(v - __half2float(hv));
        hi[j] = pack_h2(hu, hv);
        lo[j] = pack_h2(lu, lv);
    }
    *reinterpret_cast<uint4*>(g_xhi + i) = make_uint4(hi[0], hi[1], hi[2], hi[3]);
    *reinterpret_cast<uint4*>(g_xlo + i) = make_uint4(lo[0], lo[1], lo[2], lo[3]);
}

// ---- main GEMM: 8 warps, warp 32x32, 4-stage cp.async,
//      intra-warp ks fragment double buffering ----
__global__ void __launch_bounds__(256, 2)
bitlinear_gemm(const float* __restrict__ bias, float* __restrict__ out) {
    extern __shared__ unsigned char smem[];
    const uint32_t sb = smem_u32(smem);
    const int tid = threadIdx.x;
    const int wid = tid >> 5;
    const int lid = tid & 31;
    const int warp_m = wid & 3;       // 4 warps along M (32 rows each)
    const int warp_n = wid >> 2;      // 2 warps along N (32 cols each)
    const int n0 = blockIdx.x * BN;   // grid.x = 8  (n fastest -> L2 reuse of x)
    const int m0 = blockIdx.y * BM;   // grid.y = 512

    if (tid < BN) {
        reinterpret_cast<float*>(smem + OFF_BIAS)[tid] = bias[n0 + tid];
    }

    // staging roles:
    //   A: thread -> (row = tid>>1, chunk pair cp = tid&1): 2 CP16 per buffer
    //   B: thread -> (row = tid>>2, chunk = tid&3): 1 CP16 per buffer
    const int arow = tid >> 1;
    const int acp  = tid & 1;
    const int brow = tid >> 2;
    const int bch  = tid & 3;
    const __half* ah_base = g_xhi + (size_t)(m0 + arow) * K_TOTAL + acp * 16;
    const __half* al_base = g_xlo + (size_t)(m0 + arow) * K_TOTAL + acp * 16;
    const __half* b_base  = g_ST  + (size_t)(n0 + brow) * K_TOTAL + bch * 8;
    const uint32_t asw0 = sw_off(arow, acp * 2 + 0);
    const uint32_t asw1 = sw_off(arow, acp * 2 + 1);
    const uint32_t bsw  = sw_off(brow, bch);

    auto issue_stage = [&](int kb) {
        if (kb < KB_STEPS) {
            const int buf = kb % STAGES;
            const __half* ah = ah_base + kb * BK;
            const __half* al = al_base + kb * BK;
            CP16(sb + OFF_AHI(buf) + asw0, ah);
            CP16(sb + OFF_AHI(buf) + asw1, ah + 8);
            CP16(sb + OFF_ALO(buf) + asw0, al);
            CP16(sb + OFF_ALO(buf) + asw1, al + 8);
            CP16(sb + OFF_BT(buf)  + bsw,  b_base + kb * BK);
        }
        CP_COMMIT();
    };

    issue_stage(0);
    issue_stage(1);
    issue_stage(2);

    float acc[2][4][4];
    #pragma unroll
    for (int i = 0; i < 2; i++)
        #pragma unroll
        for (int j = 0; j < 4; j++)
            #pragma unroll
            for (int c = 0; c < 4; c++) acc[i][j][c] = 0.0f;

    const int fr  = lid & 15;     // ldmatrix row within 16
    const int fch = lid >> 4;     // k-half select

    // double-buffered fragments: index = ks (0/1)
    uint32_t a_hi[2][2][4], a_lo[2][2][4], bq[2][2][4];

    for (int kb = 0; kb < KB_STEPS; kb++) {
        CP_WAIT2();               // stage kb complete (2 newer groups in flight)
        __syncthreads();          // stage kb-1 fully consumed by all warps
        issue_stage(kb + 3);      // refill buf (kb-1)%4 — safe post-barrier

        const int buf = kb % STAGES;
        const uint32_t ahi = sb + OFF_AHI(buf);
        const uint32_t alo = sb + OFF_ALO(buf);
        const uint32_t bsm = sb + OFF_BT(buf);

        // ---- load ks0 fragments ----
        #pragma unroll
        for (int mt = 0; mt < 2; mt++) {
            uint32_t o = sw_off(warp_m * 32 + mt * 16 + fr, fch);
            LDSM_X4(a_hi[0][mt][0], a_hi[0][mt][1], a_hi[0][mt][2], a_hi[0][mt][3], ahi + o);
            LDSM_X4(a_lo[0][mt][0], a_lo[0][mt][1], a_lo[0][mt][2], a_lo[0][mt][3], alo + o);
        }
        #pragma unroll
        for (int p = 0; p < 2; p++) {
            uint32_t o = sw_off(warp_n * 32 + p * 16 + fr, fch);
            LDSM_X4(bq[0][p][0], bq[0][p][1], bq[0][p][2], bq[0][p][3], bsm + o);
        }

        // ---- prefetch ks1 fragments (independent of ks0 MMAs below) ----
        #pragma unroll
        for (int mt = 0; mt < 2; mt++) {
            uint32_t o = sw_off(warp_m * 32 + mt * 16 + fr, 2 + fch);
            LDSM_X4(a_hi[1][mt][0], a_hi[1][mt][1], a_hi[1][mt][2], a_hi[1][mt][3], ahi + o);
            LDSM_X4(a_lo[1][mt][0], a_lo[1][mt][1], a_lo[1][mt][2], a_lo[1][mt][3], alo + o);
        }
        #pragma unroll
        for (int p = 0; p < 2; p++) {
            uint32_t o = sw_off(warp_n * 32 + p * 16 + fr, 2 + fch);
            LDSM_X4(bq[1][p][0], bq[1][p][1], bq[1][p][2], bq[1][p][3], bsm + o);
        }

        // ---- MMAs: ks0 (hi then lo), then ks1 (hi then lo) ----
        // These overlap the in-flight ks1 LDSMs (no register dependency on ks0 set).
        #pragma unroll
        for (int ks = 0; ks < 2; ks++) {
            #pragma unroll
            for (int mt = 0; mt < 2; mt++) {
                #pragma unroll
                for (int nt = 0; nt < 4; nt++) {
                    uint32_t b0 = bq[ks][nt >> 1][nt & 1];
                    uint32_t b1 = bq[ks][nt >> 1][2 + (nt & 1)];
                    MMA16816(acc[mt][nt], a_hi[ks][mt][0], a_hi[ks][mt][1],
                             a_hi[ks][mt][2], a_hi[ks][mt][3], b0, b1);
                    MMA16816(acc[mt][nt], a_lo[ks][mt][0], a_lo[ks][mt][1],
                             a_lo[ks][mt][2], a_lo[ks][mt][3], b0, b1);
                }
            }
        }
    }

    // ---- epilogue: scale by gamma, add bias, quantize, store ----
    const float gamma = g_gamma;
    const float* bias_s = reinterpret_cast<const float*>(smem + OFF_BIAS);
    #pragma unroll
    for (int mt = 0; mt < 2; mt++) {
        int row0 = m0 + warp_m * 32 + mt * 16 + (lid >> 2);
        #pragma unroll
        for (int nt = 0; nt < 4; nt++) {
            int coln = warp_n * 32 + nt * 8 + (lid & 3) * 2;
            float b0 = bias_s[coln], b1 = bias_s[coln + 1];
            float2 v0, v1;
            v0.x = quantize(acc[mt][nt][0] * gamma + b0);
            v0.y = quantize(acc[mt][nt][1] * gamma + b1);
            v1.x = quantize(acc[mt][nt][2] * gamma + b0);
            v1.y = quantize(acc[mt][nt][3] * gamma + b1);
            *reinterpret_cast<float2*>(out + (size_t)row0 * N_TOTAL + n0 + coln) = v0;
            *reinterpret_cast<float2*>(out + (size_t)(row0 + 8) * N_TOTAL + n0 + coln) = v1;
        }
    }
}

// ---- harness entry ----
extern "C" void kernel_launch(void* const* d_in, const int* in_sizes, int n_in,
                              void* d_out, int out_size) {
    const float* x    = (const float*)d_in[0];
    const float* w    = (const float*)d_in[1];
    const float* bias = (const float*)d_in[2];
    float* out = (float*)d_out;

    cudaFuncSetAttribute(bitlinear_gemm,
                         cudaFuncAttributeMaxDynamicSharedMemorySize, SMEM_TOTAL);

    // GEMM is the 4th launch -> ncu captures it.
    reduce_rows<<<512, 256>>>(w);
    pack_signs<<<512, 512>>>(w);
    split_x<<<(M_TOTAL * K_TOTAL) / (8 * 256), 256>>>(x);

    dim3 grid(N_TOTAL / BN, M_TOTAL / BM);   // (8, 512): n fastest
    bitlinear_gemm<<<grid, 256, SMEM_TOTAL>>>(bias, out);
}

// round 16
// speedup vs baseline: 1.1567x; 1.1567x over previous
#include <cuda_runtime.h>
#include <cuda_fp16.h>
#include <cstdint>
#include <cstddef>

// ============================================================
// UUPBitLinear: out = round(clip(x @ (sign(W-mean)*gamma) + bias, -1, 1)*7)/7
//   x: [65536, 512] fp32, W: [512, 512] fp32, bias: [512] fp32
//
// HMMA mma.sync path. gamma factored out -> B operand is exact ternary fp16
// S^T. x pre-split into hi/lo fp16; fp32-accumulated two-pass MMA.
// R14: 6 small CTAs/SM (BM=64,BN=64,128 thr) — same 24 warps/SM as the
//      215us champion but 6 independent sync domains instead of 3.
//      Evidence R5-R13: tensor% tracks warps/SM and domain count; barriers
//      phase-lock warps within a CTA, so overlap comes from CTA diversity.
// ============================================================

#define M_TOTAL 65536
#define N_TOTAL 512
#define K_TOTAL 512

#define BM 64
#define BN 64
#define BK 32
#define KB_STEPS (K_TOTAL / BK)   // 16
#define STAGES 3

// dynamic smem: [0,256) bias; stages at 1024 + s*12288
//   A_hi: 64 rows x 64B = 4096 ; A_lo: 4096 ; B: 64 rows x 64B = 4096
#define OFF_BIAS   0
#define STAGE_SZ   12288
#define OFF_AHI(s) (1024 + (s) * STAGE_SZ)
#define OFF_ALO(s) (1024 + (s) * STAGE_SZ + 4096)
#define OFF_BT(s)  (1024 + (s) * STAGE_SZ + 8192)
#define SMEM_TOTAL (1024 + STAGES * STAGE_SZ)   // 37888 -> 6 CTAs/SM

// ---- device scratch (allocation-free) ----
__device__ float  g_part_sum[512];
__device__ float  g_part_abs[512];
__device__ float  g_gamma;
__device__ __half g_ST[N_TOTAL * K_TOTAL];            // S^T: [N][K] ternary fp16
__device__ __half g_xhi[(size_t)M_TOTAL * K_TOTAL];   // 64 MB
__device__ __half g_xlo[(size_t)M_TOTAL * K_TOTAL];   // 64 MB

// ---- helpers ----
__device__ __forceinline__ uint32_t smem_u32(const void* p) {
    uint32_t a;
    asm("{ .reg .u64 t; cvta.to.shared.u64 t, %1; cvt.u32.u64 %0, t; }"
        : "=r"(a) : "l"(p));
    return a;
}

// rows are 64B (32 halfs); chunk = 16B unit (0..3), swizzled so ldmatrix's
// 8-row groups hit distinct banks (validated R3-R13).
__device__ __forceinline__ uint32_t sw_off(int row, int chunk) {
    return (uint32_t)(row * 64 + (((chunk ^ ((row >> 1) & 3)) & 3) << 4));
}

#define LDSM_X4(r0, r1, r2, r3, addr)                                      \
    asm volatile("ldmatrix.sync.aligned.m8n8.x4.shared.b16 "               \
                 "{%0,%1,%2,%3}, [%4];"                                    \
                 : "=r"(r0), "=r"(r1), "=r"(r2), "=r"(r3) : "r"(addr))

#define MMA16816(d, a0, a1, a2, a3, b0, b1)                                \
    asm volatile("mma.sync.aligned.m16n8k16.row.col.f32.f16.f16.f32 "      \
                 "{%0,%1,%2,%3}, {%4,%5,%6,%7}, {%8,%9}, {%0,%1,%2,%3};"   \
                 : "+f"((d)[0]), "+f"((d)[1]), "+f"((d)[2]), "+f"((d)[3])  \
                 : "r"(a0), "r"(a1), "r"(a2), "r"(a3), "r"(b0), "r"(b1))

#define CP16(smaddr, gptr)                                                 \
    asm volatile("cp.async.cg.shared.global [%0], [%1], 16;"               \
                 :: "r"(smaddr), "l"(__cvta_generic_to_global(gptr)) : "memory")

#define CP_COMMIT() asm volatile("cp.async.commit_group;" ::: "memory")
#define CP_WAIT1()  asm volatile("cp.async.wait_group 1;" ::: "memory")

__device__ __forceinline__ uint32_t pack_h2(__half a, __half b) {
    __half2 h = __halves2half2(a, b);
    return *reinterpret_cast<uint32_t*>(&h);
}

__device__ __forceinline__ float quantize(float y) {
    y = fminf(fmaxf(y, -1.0f), 1.0f);
    return rintf(y * 7.0f) * (1.0f / 7.0f);   // round-half-even == jnp.round
}

// ---- prep 1: deterministic per-row reduction of W ----
__global__ void reduce_rows(const float* __restrict__ w) {
    __shared__ float ss[256], sa[256];
    int r = blockIdx.x, t = threadIdx.x;
    float v0 = w[r * 512 + t];
    float v1 = w[r * 512 + t + 256];
    ss[t] = v0 + v1;
    sa[t] = fabsf(v0) + fabsf(v1);
    __syncthreads();
    #pragma unroll
    for (int o = 128; o > 0; o >>= 1) {
        if (t < o) { ss[t] += ss[t + o]; sa[t] += sa[t + o]; }
        __syncthreads();
    }
    if (t == 0) { g_part_sum[r] = ss[0]; g_part_abs[r] = sa[0]; }
}

// ---- prep 2: fused final reduce + pack S^T[n][k] = sign(W[k][n]-mean) ----
__global__ void __launch_bounds__(512)
pack_signs(const float* __restrict__ w) {
    __shared__ float ss[256], sa[256];
    __shared__ float sh_mean;
    const int t = threadIdx.x;
    const int n = blockIdx.x;
    if (t < 256) {
        ss[t] = g_part_sum[t] + g_part_sum[t + 256];
        sa[t] = g_part_abs[t] + g_part_abs[t + 256];
    }
    __syncthreads();
    #pragma unroll
    for (int o = 128; o > 0; o >>= 1) {
        if (t < o) { ss[t] += ss[t + o]; sa[t] += sa[t + o]; }
        __syncthreads();
    }
    if (t == 0) {
        sh_mean = ss[0] * (1.0f / 262144.0f);
        if (n == 0) g_gamma = sa[0] * (1.0f / 262144.0f);
    }
    __syncthreads();
    const float mean = sh_mean;
    float d = w[t * 512 + n] - mean;
    float s = (d > 0.0f) ? 1.0f : ((d < 0.0f) ? -1.0f : 0.0f);
    g_ST[n * 512 + t] = __float2half(s);
}

// ---- prep 3: split x into fp16 hi/lo (exact 2-term decomposition) ----
__global__ void __launch_bounds__(256)
split_x(const float* __restrict__ x) {
    size_t i = ((size_t)blockIdx.x * 256 + threadIdx.x) * 8;
    float4 a = *reinterpret_cast<const float4*>(x + i);
    float4 b = *reinterpret_cast<const float4*>(x + i + 4);
    float f[8] = {a.x, a.y, a.z, a.w, b.x, b.y, b.z, b.w};
    uint32_t hi[4], lo[4];
    #pragma unroll
    for (int j = 0; j < 4; j++) {
        float u = f[2 * j], v = f[2 * j + 1];
        __half hu = __float2half_rn(u), hv = __float2half_rn(v);
        __half lu = __float2half_rn(u - __half2float(hu));
        __half lv = __float2half_rn(v - __half2float(hv));
        hi[j] = pack_h2(hu, hv);
        lo[j] = pack_h2(lu, lv);
    }
    *reinterpret_cast<uint4*>(g_xhi + i) = make_uint4(hi[0], hi[1], hi[2], hi[3]);
    *reinterpret_cast<uint4*>(g_xlo + i) = make_uint4(lo[0], lo[1], lo[2], lo[3]);
}

// ---- main GEMM: 64x64 CTAs, 4 warps (2m x 2n), 3-stage cp.async ----
__global__ void __launch_bounds__(128, 6)
bitlinear_gemm(const float* __restrict__ bias, float* __restrict__ out) {
    extern __shared__ unsigned char smem[];
    const uint32_t sb = smem_u32(smem);
    const int tid = threadIdx.x;
    const int wid = tid >> 5;
    const int lid = tid & 31;
    const int warp_m = wid & 1;       // 2 warps along M (32 rows each)
    const int warp_n = wid >> 1;      // 2 warps along N (32 cols each)
    const int n0 = blockIdx.x * BN;   // grid.x = 8  (n fastest -> L2 reuse of x)
    const int m0 = blockIdx.y * BM;   // grid.y = 1024

    if (tid < BN) {
        reinterpret_cast<float*>(smem + OFF_BIAS)[tid] = bias[n0 + tid];
    }

    // staging roles (128 threads, all 3 buffers 64 rows x 64B):
    //   thread -> (row = tid>>1, chunk pair cp = tid&1): 2 CP16 per buffer
    const int srow = tid >> 1;
    const int scp  = tid & 1;
    const __half* ah_base = g_xhi + (size_t)(m0 + srow) * K_TOTAL + scp * 16;
    const __half* al_base = g_xlo + (size_t)(m0 + srow) * K_TOTAL + scp * 16;
    const __half* b_base  = g_ST  + (size_t)(n0 + srow) * K_TOTAL + scp * 16;
    const uint32_t sw0 = sw_off(srow, scp * 2 + 0);
    const uint32_t sw1 = sw_off(srow, scp * 2 + 1);

    auto issue_stage = [&](int kb) {
        if (kb < KB_STEPS) {
            const int buf = kb % STAGES;
            const __half* ah = ah_base + kb * BK;
            const __half* al = al_base + kb * BK;
            const __half* bp = b_base  + kb * BK;
            CP16(sb + OFF_AHI(buf) + sw0, ah);
            CP16(sb + OFF_AHI(buf) + sw1, ah + 8);
            CP16(sb + OFF_ALO(buf) + sw0, al);
            CP16(sb + OFF_ALO(buf) + sw1, al + 8);
            CP16(sb + OFF_BT(buf)  + sw0, bp);
            CP16(sb + OFF_BT(buf)  + sw1, bp + 8);
        }
        CP_COMMIT();
    };

    issue_stage(0);
    issue_stage(1);

    float acc[2][4][4];
    #pragma unroll
    for (int i = 0; i < 2; i++)
        #pragma unroll
        for (int j = 0; j < 4; j++)
            #pragma unroll
            for (int c = 0; c < 4; c++) acc[i][j][c] = 0.0f;

    const int fr  = lid & 15;     // ldmatrix row within 16
    const int fch = lid >> 4;     // k-half select

    for (int kb = 0; kb < KB_STEPS; kb++) {
        CP_WAIT1();               // stage kb complete (1 newer group in flight)
        __syncthreads();          // stage kb-1 fully consumed by all warps
        issue_stage(kb + 2);      // refill buf (kb-1)%3 — safe post-barrier

        const int buf = kb % STAGES;
        const uint32_t ahi = sb + OFF_AHI(buf);
        const uint32_t alo = sb + OFF_ALO(buf);
        const uint32_t bsm = sb + OFF_BT(buf);

        #pragma unroll
        for (int ks = 0; ks < 2; ks++) {
            uint32_t a_hi[2][4], a_lo[2][4], bq[2][4];
            #pragma unroll
            for (int mt = 0; mt < 2; mt++) {
                int row = warp_m * 32 + mt * 16 + fr;
                uint32_t o = sw_off(row, ks * 2 + fch);
                LDSM_X4(a_hi[mt][0], a_hi[mt][1], a_hi[mt][2], a_hi[mt][3], ahi + o);
                LDSM_X4(a_lo[mt][0], a_lo[mt][1], a_lo[mt][2], a_lo[mt][3], alo + o);
            }
            #pragma unroll
            for (int p = 0; p < 2; p++) {   // 2 n-tiles per ldmatrix.x4
                int row = warp_n * 32 + p * 16 + fr;
                uint32_t o = sw_off(row, ks * 2 + fch);
                LDSM_X4(bq[p][0], bq[p][1], bq[p][2], bq[p][3], bsm + o);
            }
            #pragma unroll
            for (int mt = 0; mt < 2; mt++) {
                #pragma unroll
                for (int nt = 0; nt < 4; nt++) {
                    uint32_t b0 = bq[nt >> 1][nt & 1];
                    uint32_t b1 = bq[nt >> 1][2 + (nt & 1)];
                    MMA16816(acc[mt][nt], a_hi[mt][0], a_hi[mt][1], a_hi[mt][2], a_hi[mt][3], b0, b1);
                    MMA16816(acc[mt][nt], a_lo[mt][0], a_lo[mt][1], a_lo[mt][2], a_lo[mt][3], b0, b1);
                }
            }
        }
    }

    // ---- epilogue: scale by gamma, add bias, quantize, store ----
    const float gamma = g_gamma;
    const float* bias_s = reinterpret_cast<const float*>(smem + OFF_BIAS);
    #pragma unroll
    for (int mt = 0; mt < 2; mt++) {
        int row0 = m0 + warp_m * 32 + mt * 16 + (lid >> 2);
        #pragma unroll
        for (int nt = 0; nt < 4; nt++) {
            int coln = warp_n * 32 + nt * 8 + (lid & 3) * 2;
            float b0 = bias_s[coln], b1 = bias_s[coln + 1];
            float2 v0, v1;
            v0.x = quantize(acc[mt][nt][0] * gamma + b0);
            v0.y = quantize(acc[mt][nt][1] * gamma + b1);
            v1.x = quantize(acc[mt][nt][2] * gamma + b0);
            v1.y = quantize(acc[mt][nt][3] * gamma + b1);
            *reinterpret_cast<float2*>(out + (size_t)row0 * N_TOTAL + n0 + coln) = v0;
            *reinterpret_cast<float2*>(out + (size_t)(row0 + 8) * N_TOTAL + n0 + coln) = v1;
        }
    }
}

// ---- harness entry ----
extern "C" void kernel_launch(void* const* d_in, const int* in_sizes, int n_in,
                              void* d_out, int out_size) {
    const float* x    = (const float*)d_in[0];
    const float* w    = (const float*)d_in[1];
    const float* bias = (const float*)d_in[2];
    float* out = (float*)d_out;

    cudaFuncSetAttribute(bitlinear_gemm,
                         cudaFuncAttributeMaxDynamicSharedMemorySize, SMEM_TOTAL);

    // GEMM is the 4th launch -> ncu captures it.
    reduce_rows<<<512, 256>>>(w);
    pack_signs<<<512, 512>>>(w);
    split_x<<<(M_TOTAL * K_TOTAL) / (8 * 256), 256>>>(x);

    dim3 grid(N_TOTAL / BN, M_TOTAL / BM);   // (8, 1024): n fastest
    bitlinear_gemm<<<grid, 128, SMEM_TOTAL>>>(bias, out);
}